// round 12
// baseline (speedup 1.0000x reference)
#include <cuda_runtime.h>
#include <cuda_fp16.h>
#include <math.h>
#include <stdint.h>

#define B_DIM 4096
#define IN_DIM 512
#define H_DIM 1024
#define NGATE (4 * H_DIM)          // 4096
#define KTOT  (IN_DIM + H_DIM)     // 1536
#define KC 32                      // K per stage (fp16)
#define NSTAGE (KTOT / KC)         // 48

#define M_T 3200                   // rows done by tensor path (25 x 128)
#define M_F (B_DIM - M_T)          // 896 rows done by FFMA path (14 x 64)

// fp16 hi/lo split copies of A = [input | hx] and B = permuted [Wxh | Whh]
__device__ __align__(16) __half g_Ah[(size_t)B_DIM * KTOT];
__device__ __align__(16) __half g_Al[(size_t)B_DIM * KTOT];
__device__ __align__(16) __half g_Bh[(size_t)NGATE * KTOT];
__device__ __align__(16) __half g_Bl[(size_t)NGATE * KTOT];
// fp32 gates scratch for the FFMA rows
__device__ __align__(16) float g_gates[(size_t)M_F * NGATE];

// ---------------- asm helpers (sm_80-compatible PTX only) ----------------

__device__ __forceinline__ uint32_t smem_u32(const void* p) {
    uint32_t a;
    asm("{ .reg .u64 t; cvta.to.shared.u64 t, %1; cvt.u32.u64 %0, t; }"
        : "=r"(a) : "l"(p));
    return a;
}

__device__ __forceinline__ void cpasync16(uint32_t dst, const void* src) {
    asm volatile("cp.async.cg.shared.global [%0], [%1], 16;"
                 :: "r"(dst), "l"(__cvta_generic_to_global(src)) : "memory");
}
#define CP_COMMIT() asm volatile("cp.async.commit_group;" ::: "memory")
#define CP_WAIT(n)  asm volatile("cp.async.wait_group %0;" :: "n"(n) : "memory")

__device__ __forceinline__ void ldsm_x4(uint32_t& r0, uint32_t& r1,
                                        uint32_t& r2, uint32_t& r3, uint32_t a) {
    asm volatile("ldmatrix.sync.aligned.m8n8.x4.shared.b16 {%0,%1,%2,%3}, [%4];"
                 : "=r"(r0), "=r"(r1), "=r"(r2), "=r"(r3) : "r"(a));
}

__device__ __forceinline__ void mma_f16(float* d, const uint32_t* a,
                                        const uint32_t* b) {
    asm volatile(
        "mma.sync.aligned.m16n8k16.row.col.f32.f16.f16.f32 "
        "{%0,%1,%2,%3}, {%4,%5,%6,%7}, {%8,%9}, {%0,%1,%2,%3};"
        : "+f"(d[0]), "+f"(d[1]), "+f"(d[2]), "+f"(d[3])
        : "r"(a[0]), "r"(a[1]), "r"(a[2]), "r"(a[3]), "r"(b[0]), "r"(b[1]));
}

__device__ __forceinline__ float sigf(float x) { return 1.0f / (1.0f + expf(-x)); }

// ---------------- fused prep kernel (A rows [0,M_T) + all B) ----------------

struct alignas(16) Hf8 { __half h[8]; };

__device__ __forceinline__ void split8(const float* f, Hf8& hi, Hf8& lo) {
#pragma unroll
    for (int e = 0; e < 8; e++) {
        __half h = __float2half_rn(f[e]);
        hi.h[e] = h;
        lo.h[e] = __float2half_rn(f[e] - __half2float(h));
    }
}

#define PREP_A_BLOCKS (M_T * 192 / 256)          // 2400
#define PREP_BLOCKS   (PREP_A_BLOCKS + 3072)     // 5472

__global__ __launch_bounds__(256) void prep_kernel(
    const float* __restrict__ input, const float* __restrict__ hx,
    const float* __restrict__ Wxh, const float* __restrict__ Whh)
{
    int bid = blockIdx.x;
    if (bid < PREP_A_BLOCKS) {
        int idx = bid * 256 + threadIdx.x;
        int row = idx / 192;
        int k = (idx % 192) * 8;
        const float* src = (k < IN_DIM) ? (input + (size_t)row * IN_DIM + k)
                                        : (hx + (size_t)row * H_DIM + (k - IN_DIM));
        float f[8];
        float4 v0 = ((const float4*)src)[0];
        float4 v1 = ((const float4*)src)[1];
        f[0]=v0.x; f[1]=v0.y; f[2]=v0.z; f[3]=v0.w;
        f[4]=v1.x; f[5]=v1.y; f[6]=v1.z; f[7]=v1.w;
        Hf8 hi, lo; split8(f, hi, lo);
        *(uint4*)&g_Ah[(size_t)row * KTOT + k] = *(const uint4*)&hi;
        *(uint4*)&g_Al[(size_t)row * KTOT + k] = *(const uint4*)&lo;
    } else {
        int idx = (bid - PREP_A_BLOCKS) * 256 + threadIdx.x;
        int rowp = idx / 192;                 // row' = (h>>3)*32 + g*8 + (h&7)
        int k = (idx % 192) * 8;
        int g = (rowp >> 3) & 3;
        int h = ((rowp >> 5) << 3) | (rowp & 7);
        int orig = g * H_DIM + h;
        const float* src = (k < IN_DIM) ? (Wxh + (size_t)orig * IN_DIM + k)
                                        : (Whh + (size_t)orig * H_DIM + (k - IN_DIM));
        float f[8];
        float4 v0 = ((const float4*)src)[0];
        float4 v1 = ((const float4*)src)[1];
        f[0]=v0.x; f[1]=v0.y; f[2]=v0.z; f[3]=v0.w;
        f[4]=v1.x; f[5]=v1.y; f[6]=v1.z; f[7]=v1.w;
        Hf8 hi, lo; split8(f, hi, lo);
        *(uint4*)&g_Bh[(size_t)rowp * KTOT + k] = *(const uint4*)&hi;
        *(uint4*)&g_Bl[(size_t)rowp * KTOT + k] = *(const uint4*)&lo;
    }
}

// ---------------- tensor-path GEMM + fused epilogue (rows [0, M_T)) --------

#define ROW_B 80                       // 64B data + 16B pad (conflict-free)
#define ATILE (128 * ROW_B)            // 10240
#define BTILE (64 * ROW_B)             // 5120
#define STAGE_SZ (2 * ATILE + 2 * BTILE)   // 30720
#define NRING 3
#define SMEM_BYTES (NRING * STAGE_SZ)  // 92160

__global__ __launch_bounds__(256, 2) void gemm_fused_kernel(
    const float* __restrict__ time_, const float* __restrict__ cx,
    const float* __restrict__ tau, const float* __restrict__ s,
    const float* __restrict__ alpha_p, const float* __restrict__ rho_p,
    const float* __restrict__ bias, float* __restrict__ out)
{
    extern __shared__ char smem[];
    const uint32_t sb = smem_u32(smem);
    const int tid = threadIdx.x;
    const int wid = tid >> 5;
    const int lane = tid & 31;
    const int wm = wid >> 1;
    const int wn = wid & 1;

    const int m0 = blockIdx.y * 128;
    const int n0 = blockIdx.x * 64;

    const int g_row = tid >> 2;
    const int g_c4  = tid & 3;
    const uint32_t st_off   = (uint32_t)g_row * ROW_B + g_c4 * 16;
    const uint32_t st_off64 = st_off + 64 * ROW_B;
    const int g_kelem = g_c4 * 8;

    const __half* pAh  = g_Ah + (size_t)(m0 + g_row) * KTOT + g_kelem;
    const __half* pAl  = g_Al + (size_t)(m0 + g_row) * KTOT + g_kelem;
    const size_t row64 = (size_t)64 * KTOT;
    const __half* pBh  = g_Bh + (size_t)(n0 + g_row) * KTOT + g_kelem;
    const __half* pBl  = g_Bl + (size_t)(n0 + g_row) * KTOT + g_kelem;

    const int l15 = lane & 15;
    uint32_t a_off[2];
#pragma unroll
    for (int i = 0; i < 2; i++)
        a_off[i] = (uint32_t)(wm * 32 + i * 16 + l15) * ROW_B + (lane >> 4) * 16;
    uint32_t b_off[2];
    {
        int l7 = lane & 7;
        int rhalf = (lane >> 4) & 1;
        int chalf = (lane >> 3) & 1;
#pragma unroll
        for (int j = 0; j < 2; j++)
            b_off[j] = (uint32_t)(wn * 32 + j * 16 + rhalf * 8 + l7) * ROW_B + chalf * 16;
    }

    float acc[2][4][4];
#pragma unroll
    for (int i = 0; i < 2; i++)
#pragma unroll
        for (int nb = 0; nb < 4; nb++)
#pragma unroll
            for (int e = 0; e < 4; e++) acc[i][nb][e] = 0.0f;

#define ISSUE_STAGE(C, BUF) do {                                            \
    uint32_t base_ = sb + (uint32_t)(BUF) * STAGE_SZ;                       \
    size_t ke_ = (size_t)(C) * KC;                                          \
    cpasync16(base_ + st_off,                      pAh + ke_);              \
    cpasync16(base_ + st_off64,                    pAh + row64 + ke_);      \
    cpasync16(base_ + ATILE + st_off,              pAl + ke_);              \
    cpasync16(base_ + ATILE + st_off64,            pAl + row64 + ke_);      \
    cpasync16(base_ + 2*ATILE + st_off,            pBh + ke_);              \
    cpasync16(base_ + 2*ATILE + BTILE + st_off,    pBl + ke_);              \
    CP_COMMIT();                                                            \
} while (0)

    ISSUE_STAGE(0, 0);
    ISSUE_STAGE(1, 1);

    for (int c = 0; c < NSTAGE; c++) {
        const int buf = c % 3;
        if (c + 1 < NSTAGE) { CP_WAIT(1); }
        else                { CP_WAIT(0); }
        __syncthreads();
        if (c + 2 < NSTAGE)
            ISSUE_STAGE(c + 2, (c + 2) % 3);

        const uint32_t ahb = sb + (uint32_t)buf * STAGE_SZ;
        const uint32_t alb = ahb + ATILE;
        const uint32_t bhb = ahb + 2 * ATILE;
        const uint32_t blb = bhb + BTILE;

#pragma unroll
        for (int ks = 0; ks < 2; ks++) {
            const uint32_t ko = ks * 32;
            uint32_t ah[2][4], al[2][4], bh[4][2], bl[4][2];
#pragma unroll
            for (int j = 0; j < 2; j++)
                ldsm_x4(bh[2*j][0], bh[2*j][1], bh[2*j+1][0], bh[2*j+1][1],
                        bhb + b_off[j] + ko);
#pragma unroll
            for (int i = 0; i < 2; i++)
                ldsm_x4(ah[i][0], ah[i][1], ah[i][2], ah[i][3],
                        ahb + a_off[i] + ko);
#pragma unroll
            for (int j = 0; j < 2; j++)
                ldsm_x4(bl[2*j][0], bl[2*j][1], bl[2*j+1][0], bl[2*j+1][1],
                        blb + b_off[j] + ko);
#pragma unroll
            for (int i = 0; i < 2; i++)
                ldsm_x4(al[i][0], al[i][1], al[i][2], al[i][3],
                        alb + a_off[i] + ko);

#pragma unroll
            for (int i = 0; i < 2; i++)
#pragma unroll
                for (int nb = 0; nb < 4; nb++)
                    mma_f16(acc[i][nb], ah[i], bh[nb]);
#pragma unroll
            for (int i = 0; i < 2; i++)
#pragma unroll
                for (int nb = 0; nb < 4; nb++)
                    mma_f16(acc[i][nb], ah[i], bl[nb]);
#pragma unroll
            for (int i = 0; i < 2; i++)
#pragma unroll
                for (int nb = 0; nb < 4; nb++)
                    mma_f16(acc[i][nb], al[i], bh[nb]);
        }
    }

    const int t = lane & 3;
    const int grow = lane >> 2;
    const int hb = ((n0 + wn * 32) >> 2) + 2 * t;

    const float alpha = alpha_p[0];
    const float rho = rho_p[0];
    const float inv_rho = 2.0f / rho;
    const float tu[2] = {tau[hb], tau[hb + 1]};
    const float sh[2] = {s[hb], s[hb + 1]};
    float bi[4][2];
#pragma unroll
    for (int g = 0; g < 4; g++) {
        bi[g][0] = bias[g * H_DIM + hb];
        bi[g][1] = bias[g * H_DIM + hb + 1];
    }

#pragma unroll
    for (int i = 0; i < 2; i++) {
#pragma unroll
        for (int rsel = 0; rsel < 2; rsel++) {
            const int r = m0 + wm * 32 + i * 16 + grow + rsel * 8;
            const float tt = time_[r];
            const float2 cx2 = *(const float2*)&cx[(size_t)r * H_DIM + hb];
            const float cxa[2] = {cx2.x, cx2.y};
            float hy2[2], cy2[2];
#pragma unroll
            for (int e = 0; e < 2; e++) {
                const int d = rsel * 2 + e;
                float gi = acc[i][0][d] + bi[0][e];
                float gf = acc[i][1][d] + bi[1][e];
                float gg = acc[i][2][d] + bi[2][e];
                float go = acc[i][3][d] + bi[3][e];
                float phi = fmodf(tt - sh[e], tu[e]) / tu[e];
                float kg;
                if (phi < 0.5f * rho)      kg = phi * inv_rho;
                else if (phi < rho)        kg = 2.0f - phi * inv_rho;
                else                       kg = alpha * phi;
                float ft = sigf(gf + 1.0f - kg);
                float it = sigf(gi) * kg;
                float gt = tanhf(gg) * kg;
                float ot = sigf(go) * kg;
                float cyv = ft * cxa[e] + it * gt;
                cy2[e] = cyv;
                hy2[e] = ot * tanhf(cyv);
            }
            *(float2*)&out[(size_t)r * H_DIM + hb] = make_float2(hy2[0], hy2[1]);
            *(float2*)&out[(size_t)B_DIM * H_DIM + (size_t)r * H_DIM + hb] =
                make_float2(cy2[0], cy2[1]);
        }
    }
}

// ---------------- FFMA-path GEMM (rows [M_T, B_DIM), exact fp32) ----------
// 64x64 tile, 256 threads (16x16), TM=TN=4 — lean regs for co-residency.

__global__ __launch_bounds__(256) void ffma_gemm_kernel(
    const float* __restrict__ input, const float* __restrict__ hx,
    const float* __restrict__ Wxh, const float* __restrict__ Whh,
    const float* __restrict__ bias)
{
    __shared__ float As[16][64];
    __shared__ float Bs[16][64];

    const int tid = threadIdx.x;
    const int tx = tid & 15;
    const int ty = tid >> 4;
    const int block_m = M_T + blockIdx.y * 64;
    const int block_n = blockIdx.x * 64;

    const int l_row = tid >> 2;         // 0..63
    const int l_kq  = (tid & 3) * 4;    // 0,4,8,12

    float acc[4][4];
#pragma unroll
    for (int i = 0; i < 4; i++)
#pragma unroll
        for (int j = 0; j < 4; j++) acc[i][j] = 0.0f;

    for (int k0 = 0; k0 < KTOT; k0 += 16) {
        const float* Ap; const float* Bp;
        int lda, ka;
        if (k0 < IN_DIM) { Ap = input; Bp = Wxh; lda = IN_DIM; ka = k0; }
        else             { Ap = hx;    Bp = Whh; lda = H_DIM;  ka = k0 - IN_DIM; }

        float4 va = *reinterpret_cast<const float4*>(
            Ap + (size_t)(block_m + l_row) * lda + ka + l_kq);
        As[l_kq + 0][l_row] = va.x; As[l_kq + 1][l_row] = va.y;
        As[l_kq + 2][l_row] = va.z; As[l_kq + 3][l_row] = va.w;
        float4 vb = *reinterpret_cast<const float4*>(
            Bp + (size_t)(block_n + l_row) * lda + ka + l_kq);
        Bs[l_kq + 0][l_row] = vb.x; Bs[l_kq + 1][l_row] = vb.y;
        Bs[l_kq + 2][l_row] = vb.z; Bs[l_kq + 3][l_row] = vb.w;
        __syncthreads();

#pragma unroll
        for (int k = 0; k < 16; k++) {
            float a[4], b[4];
#pragma unroll
            for (int i = 0; i < 4; i++) a[i] = As[k][ty * 4 + i];
#pragma unroll
            for (int j = 0; j < 4; j++) b[j] = Bs[k][tx * 4 + j];
#pragma unroll
            for (int i = 0; i < 4; i++)
#pragma unroll
                for (int j = 0; j < 4; j++)
                    acc[i][j] = fmaf(a[i], b[j], acc[i][j]);
        }
        __syncthreads();
    }

#pragma unroll
    for (int i = 0; i < 4; i++) {
        size_t m = block_m + ty * 4 + i;
        int n = block_n + tx * 4;
        float4 v;
        v.x = acc[i][0] + bias[n + 0];
        v.y = acc[i][1] + bias[n + 1];
        v.z = acc[i][2] + bias[n + 2];
        v.w = acc[i][3] + bias[n + 3];
        *reinterpret_cast<float4*>(&g_gates[(m - M_T) * NGATE + n]) = v;
    }
}

// ---------------- eltwise tail for FFMA rows ----------------

__global__ __launch_bounds__(256) void eltwise_tail_kernel(
    const float* __restrict__ time_, const float* __restrict__ cx,
    const float* __restrict__ tau, const float* __restrict__ s,
    const float* __restrict__ alpha_p, const float* __restrict__ rho_p,
    float* __restrict__ out)
{
    int idx = blockIdx.x * 256 + threadIdx.x;
    if (idx >= M_F * H_DIM) return;
    int b = M_T + (idx >> 10);
    int h = idx & (H_DIM - 1);

    float t = time_[b];
    float tu = tau[h];
    float phi = fmodf(t - s[h], tu) / tu;
    float alpha = alpha_p[0], rho = rho_p[0];
    float kg;
    if (phi < 0.5f * rho)      kg = 2.0f * phi / rho;
    else if (phi < rho)        kg = 2.0f - 2.0f * phi / rho;
    else                       kg = alpha * phi;

    const float* grow = g_gates + (size_t)(b - M_T) * NGATE + h;
    float gi = grow[0];
    float gf = grow[H_DIM];
    float gg = grow[2 * H_DIM];
    float go = grow[3 * H_DIM];

    float ft = sigf(gf + 1.0f - kg);
    float it = sigf(gi) * kg;
    float gt = tanhf(gg) * kg;
    float ot = sigf(go) * kg;

    float c = cx[(size_t)b * H_DIM + h];
    float cy = ft * c + it * gt;
    float hy = ot * tanhf(cy);

    out[(size_t)b * H_DIM + h] = hy;
    out[(size_t)B_DIM * H_DIM + (size_t)b * H_DIM + h] = cy;
}

// ---------------- launch (fork-join, two concurrent branches) -------------

extern "C" void kernel_launch(void* const* d_in, const int* in_sizes, int n_in,
                              void* d_out, int out_size) {
    const float* input = (const float*)d_in[0];
    const float* time_ = (const float*)d_in[1];
    const float* hx    = (const float*)d_in[2];
    const float* cx    = (const float*)d_in[3];
    const float* Wxh_w = (const float*)d_in[4];
    const float* Wxh_b = (const float*)d_in[5];
    const float* Whh_w = (const float*)d_in[6];
    const float* tau   = (const float*)d_in[7];
    const float* s     = (const float*)d_in[8];
    const float* alpha = (const float*)d_in[9];
    const float* rho   = (const float*)d_in[10];
    float* out = (float*)d_out;

    // One-time resource init (first call is the uncaptured correctness run;
    // work issued per call is identical and deterministic).
    static cudaStream_t s1 = nullptr;
    static cudaEvent_t evF = nullptr, evJ = nullptr;
    if (s1 == nullptr) {
        cudaStreamCreateWithFlags(&s1, cudaStreamNonBlocking);
        cudaEventCreateWithFlags(&evF, cudaEventDisableTiming);
        cudaEventCreateWithFlags(&evJ, cudaEventDisableTiming);
        cudaFuncSetAttribute(gemm_fused_kernel,
                             cudaFuncAttributeMaxDynamicSharedMemorySize,
                             SMEM_BYTES);
    }

    // Fork: branch s1 runs prep + tensor GEMM; main stream runs FFMA path.
    cudaEventRecord(evF, 0);
    cudaStreamWaitEvent(s1, evF, 0);

    prep_kernel<<<PREP_BLOCKS, 256, 0, s1>>>(input, hx, Wxh_w, Whh_w);
    {
        dim3 grid(NGATE / 64, M_T / 128);   // 64 x 25
        gemm_fused_kernel<<<grid, 256, SMEM_BYTES, s1>>>(
            time_, cx, tau, s, alpha, rho, Wxh_b, out);
    }
    cudaEventRecord(evJ, s1);

    {
        dim3 grid(NGATE / 64, M_F / 64);    // 64 x 14
        ffma_gemm_kernel<<<grid, 256>>>(input, hx, Wxh_w, Whh_w, Wxh_b);
    }
    eltwise_tail_kernel<<<(M_F * H_DIM + 255) / 256, 256>>>(
        time_, cx, tau, s, alpha, rho, out);

    // Join: main stream completion implies both branches done.
    cudaStreamWaitEvent(0, evJ, 0);
}

// round 13
// speedup vs baseline: 1.2016x; 1.2016x over previous
#include <cuda_runtime.h>
#include <cuda_fp16.h>
#include <math.h>
#include <stdint.h>

#define B_DIM 4096
#define IN_DIM 512
#define H_DIM 1024
#define NGATE (4 * H_DIM)          // 4096
#define KTOT  (IN_DIM + H_DIM)     // 1536
#define KC 32                      // K per stage (fp16)
#define NSTAGE (KTOT / KC)         // 48

#define M_T 3456                   // rows on tensor path (27 x 128)
#define M_F (B_DIM - M_T)          // 640 rows on FFMA path (5 x 128)

// fp16 hi/lo split copies of A = [input | hx] and B = permuted [Wxh | Whh]
__device__ __align__(16) __half g_Ah[(size_t)B_DIM * KTOT];
__device__ __align__(16) __half g_Al[(size_t)B_DIM * KTOT];
__device__ __align__(16) __half g_Bh[(size_t)NGATE * KTOT];
__device__ __align__(16) __half g_Bl[(size_t)NGATE * KTOT];
// fp32 gates scratch for the FFMA rows
__device__ __align__(16) float g_gates[(size_t)M_F * NGATE];

// ---------------- asm helpers (sm_80-compatible PTX only) ----------------

__device__ __forceinline__ uint32_t smem_u32(const void* p) {
    uint32_t a;
    asm("{ .reg .u64 t; cvta.to.shared.u64 t, %1; cvt.u32.u64 %0, t; }"
        : "=r"(a) : "l"(p));
    return a;
}

__device__ __forceinline__ void cpasync16(uint32_t dst, const void* src) {
    asm volatile("cp.async.cg.shared.global [%0], [%1], 16;"
                 :: "r"(dst), "l"(__cvta_generic_to_global(src)) : "memory");
}
#define CP_COMMIT() asm volatile("cp.async.commit_group;" ::: "memory")
#define CP_WAIT(n)  asm volatile("cp.async.wait_group %0;" :: "n"(n) : "memory")

__device__ __forceinline__ void ldsm_x4(uint32_t& r0, uint32_t& r1,
                                        uint32_t& r2, uint32_t& r3, uint32_t a) {
    asm volatile("ldmatrix.sync.aligned.m8n8.x4.shared.b16 {%0,%1,%2,%3}, [%4];"
                 : "=r"(r0), "=r"(r1), "=r"(r2), "=r"(r3) : "r"(a));
}

__device__ __forceinline__ void mma_f16(float* d, const uint32_t* a,
                                        const uint32_t* b) {
    asm volatile(
        "mma.sync.aligned.m16n8k16.row.col.f32.f16.f16.f32 "
        "{%0,%1,%2,%3}, {%4,%5,%6,%7}, {%8,%9}, {%0,%1,%2,%3};"
        : "+f"(d[0]), "+f"(d[1]), "+f"(d[2]), "+f"(d[3])
        : "r"(a[0]), "r"(a[1]), "r"(a[2]), "r"(a[3]), "r"(b[0]), "r"(b[1]));
}

__device__ __forceinline__ float sigf(float x) { return 1.0f / (1.0f + expf(-x)); }

// ---------------- fused prep kernel (A rows [0,M_T) + all B) ----------------

struct alignas(16) Hf8 { __half h[8]; };

__device__ __forceinline__ void split8(const float* f, Hf8& hi, Hf8& lo) {
#pragma unroll
    for (int e = 0; e < 8; e++) {
        __half h = __float2half_rn(f[e]);
        hi.h[e] = h;
        lo.h[e] = __float2half_rn(f[e] - __half2float(h));
    }
}

#define PREP_A_BLOCKS (M_T * 192 / 256)          // 2592
#define PREP_BLOCKS   (PREP_A_BLOCKS + 3072)     // 5664

__global__ __launch_bounds__(256) void prep_kernel(
    const float* __restrict__ input, const float* __restrict__ hx,
    const float* __restrict__ Wxh, const float* __restrict__ Whh)
{
    int bid = blockIdx.x;
    if (bid < PREP_A_BLOCKS) {
        int idx = bid * 256 + threadIdx.x;
        int row = idx / 192;
        int k = (idx % 192) * 8;
        const float* src = (k < IN_DIM) ? (input + (size_t)row * IN_DIM + k)
                                        : (hx + (size_t)row * H_DIM + (k - IN_DIM));
        float f[8];
        float4 v0 = ((const float4*)src)[0];
        float4 v1 = ((const float4*)src)[1];
        f[0]=v0.x; f[1]=v0.y; f[2]=v0.z; f[3]=v0.w;
        f[4]=v1.x; f[5]=v1.y; f[6]=v1.z; f[7]=v1.w;
        Hf8 hi, lo; split8(f, hi, lo);
        *(uint4*)&g_Ah[(size_t)row * KTOT + k] = *(const uint4*)&hi;
        *(uint4*)&g_Al[(size_t)row * KTOT + k] = *(const uint4*)&lo;
    } else {
        int idx = (bid - PREP_A_BLOCKS) * 256 + threadIdx.x;
        int rowp = idx / 192;                 // row' = (h>>3)*32 + g*8 + (h&7)
        int k = (idx % 192) * 8;
        int g = (rowp >> 3) & 3;
        int h = ((rowp >> 5) << 3) | (rowp & 7);
        int orig = g * H_DIM + h;
        const float* src = (k < IN_DIM) ? (Wxh + (size_t)orig * IN_DIM + k)
                                        : (Whh + (size_t)orig * H_DIM + (k - IN_DIM));
        float f[8];
        float4 v0 = ((const float4*)src)[0];
        float4 v1 = ((const float4*)src)[1];
        f[0]=v0.x; f[1]=v0.y; f[2]=v0.z; f[3]=v0.w;
        f[4]=v1.x; f[5]=v1.y; f[6]=v1.z; f[7]=v1.w;
        Hf8 hi, lo; split8(f, hi, lo);
        *(uint4*)&g_Bh[(size_t)rowp * KTOT + k] = *(const uint4*)&hi;
        *(uint4*)&g_Bl[(size_t)rowp * KTOT + k] = *(const uint4*)&lo;
    }
}

// ---------------- tensor-path GEMM + fused epilogue (rows [0, M_T)) --------

#define ROW_B 80                       // 64B data + 16B pad (conflict-free)
#define ATILE (128 * ROW_B)            // 10240
#define BTILE (64 * ROW_B)             // 5120
#define STAGE_SZ (2 * ATILE + 2 * BTILE)   // 30720
#define NRING 3
#define SMEM_BYTES (NRING * STAGE_SZ)  // 92160

__global__ __launch_bounds__(256, 2) void gemm_fused_kernel(
    const float* __restrict__ time_, const float* __restrict__ cx,
    const float* __restrict__ tau, const float* __restrict__ s,
    const float* __restrict__ alpha_p, const float* __restrict__ rho_p,
    const float* __restrict__ bias, float* __restrict__ out)
{
    extern __shared__ char smem[];
    const uint32_t sb = smem_u32(smem);
    const int tid = threadIdx.x;
    const int wid = tid >> 5;
    const int lane = tid & 31;
    const int wm = wid >> 1;
    const int wn = wid & 1;

    const int m0 = blockIdx.y * 128;
    const int n0 = blockIdx.x * 64;

    const int g_row = tid >> 2;
    const int g_c4  = tid & 3;
    const uint32_t st_off   = (uint32_t)g_row * ROW_B + g_c4 * 16;
    const uint32_t st_off64 = st_off + 64 * ROW_B;
    const int g_kelem = g_c4 * 8;

    const __half* pAh  = g_Ah + (size_t)(m0 + g_row) * KTOT + g_kelem;
    const __half* pAl  = g_Al + (size_t)(m0 + g_row) * KTOT + g_kelem;
    const size_t row64 = (size_t)64 * KTOT;
    const __half* pBh  = g_Bh + (size_t)(n0 + g_row) * KTOT + g_kelem;
    const __half* pBl  = g_Bl + (size_t)(n0 + g_row) * KTOT + g_kelem;

    const int l15 = lane & 15;
    uint32_t a_off[2];
#pragma unroll
    for (int i = 0; i < 2; i++)
        a_off[i] = (uint32_t)(wm * 32 + i * 16 + l15) * ROW_B + (lane >> 4) * 16;
    uint32_t b_off[2];
    {
        int l7 = lane & 7;
        int rhalf = (lane >> 4) & 1;
        int chalf = (lane >> 3) & 1;
#pragma unroll
        for (int j = 0; j < 2; j++)
            b_off[j] = (uint32_t)(wn * 32 + j * 16 + rhalf * 8 + l7) * ROW_B + chalf * 16;
    }

    float acc[2][4][4];
#pragma unroll
    for (int i = 0; i < 2; i++)
#pragma unroll
        for (int nb = 0; nb < 4; nb++)
#pragma unroll
            for (int e = 0; e < 4; e++) acc[i][nb][e] = 0.0f;

#define ISSUE_STAGE(C, BUF) do {                                            \
    uint32_t base_ = sb + (uint32_t)(BUF) * STAGE_SZ;                       \
    size_t ke_ = (size_t)(C) * KC;                                          \
    cpasync16(base_ + st_off,                      pAh + ke_);              \
    cpasync16(base_ + st_off64,                    pAh + row64 + ke_);      \
    cpasync16(base_ + ATILE + st_off,              pAl + ke_);              \
    cpasync16(base_ + ATILE + st_off64,            pAl + row64 + ke_);      \
    cpasync16(base_ + 2*ATILE + st_off,            pBh + ke_);              \
    cpasync16(base_ + 2*ATILE + BTILE + st_off,    pBl + ke_);              \
    CP_COMMIT();                                                            \
} while (0)

    ISSUE_STAGE(0, 0);
    ISSUE_STAGE(1, 1);

    for (int c = 0; c < NSTAGE; c++) {
        const int buf = c % 3;
        if (c + 1 < NSTAGE) { CP_WAIT(1); }
        else                { CP_WAIT(0); }
        __syncthreads();
        if (c + 2 < NSTAGE)
            ISSUE_STAGE(c + 2, (c + 2) % 3);

        const uint32_t ahb = sb + (uint32_t)buf * STAGE_SZ;
        const uint32_t alb = ahb + ATILE;
        const uint32_t bhb = ahb + 2 * ATILE;
        const uint32_t blb = bhb + BTILE;

#pragma unroll
        for (int ks = 0; ks < 2; ks++) {
            const uint32_t ko = ks * 32;
            uint32_t ah[2][4], al[2][4], bh[4][2], bl[4][2];
#pragma unroll
            for (int j = 0; j < 2; j++)
                ldsm_x4(bh[2*j][0], bh[2*j][1], bh[2*j+1][0], bh[2*j+1][1],
                        bhb + b_off[j] + ko);
#pragma unroll
            for (int i = 0; i < 2; i++)
                ldsm_x4(ah[i][0], ah[i][1], ah[i][2], ah[i][3],
                        ahb + a_off[i] + ko);
#pragma unroll
            for (int j = 0; j < 2; j++)
                ldsm_x4(bl[2*j][0], bl[2*j][1], bl[2*j+1][0], bl[2*j+1][1],
                        blb + b_off[j] + ko);
#pragma unroll
            for (int i = 0; i < 2; i++)
                ldsm_x4(al[i][0], al[i][1], al[i][2], al[i][3],
                        alb + a_off[i] + ko);

#pragma unroll
            for (int i = 0; i < 2; i++)
#pragma unroll
                for (int nb = 0; nb < 4; nb++)
                    mma_f16(acc[i][nb], ah[i], bh[nb]);
#pragma unroll
            for (int i = 0; i < 2; i++)
#pragma unroll
                for (int nb = 0; nb < 4; nb++)
                    mma_f16(acc[i][nb], ah[i], bl[nb]);
#pragma unroll
            for (int i = 0; i < 2; i++)
#pragma unroll
                for (int nb = 0; nb < 4; nb++)
                    mma_f16(acc[i][nb], al[i], bh[nb]);
        }
    }

    const int t = lane & 3;
    const int grow = lane >> 2;
    const int hb = ((n0 + wn * 32) >> 2) + 2 * t;

    const float alpha = alpha_p[0];
    const float rho = rho_p[0];
    const float inv_rho = 2.0f / rho;
    const float tu[2] = {tau[hb], tau[hb + 1]};
    const float sh[2] = {s[hb], s[hb + 1]};
    float bi[4][2];
#pragma unroll
    for (int g = 0; g < 4; g++) {
        bi[g][0] = bias[g * H_DIM + hb];
        bi[g][1] = bias[g * H_DIM + hb + 1];
    }

#pragma unroll
    for (int i = 0; i < 2; i++) {
#pragma unroll
        for (int rsel = 0; rsel < 2; rsel++) {
            const int r = m0 + wm * 32 + i * 16 + grow + rsel * 8;
            const float tt = time_[r];
            const float2 cx2 = *(const float2*)&cx[(size_t)r * H_DIM + hb];
            const float cxa[2] = {cx2.x, cx2.y};
            float hy2[2], cy2[2];
#pragma unroll
            for (int e = 0; e < 2; e++) {
                const int d = rsel * 2 + e;
                float gi = acc[i][0][d] + bi[0][e];
                float gf = acc[i][1][d] + bi[1][e];
                float gg = acc[i][2][d] + bi[2][e];
                float go = acc[i][3][d] + bi[3][e];
                float phi = fmodf(tt - sh[e], tu[e]) / tu[e];
                float kg;
                if (phi < 0.5f * rho)      kg = phi * inv_rho;
                else if (phi < rho)        kg = 2.0f - phi * inv_rho;
                else                       kg = alpha * phi;
                float ft = sigf(gf + 1.0f - kg);
                float it = sigf(gi) * kg;
                float gt = tanhf(gg) * kg;
                float ot = sigf(go) * kg;
                float cyv = ft * cxa[e] + it * gt;
                cy2[e] = cyv;
                hy2[e] = ot * tanhf(cyv);
            }
            *(float2*)&out[(size_t)r * H_DIM + hb] = make_float2(hy2[0], hy2[1]);
            *(float2*)&out[(size_t)B_DIM * H_DIM + (size_t)r * H_DIM + hb] =
                make_float2(cy2[0], cy2[1]);
        }
    }
}

// ---------------- FFMA-path GEMM (rows [M_T, B_DIM), exact fp32) ----------
// R1's proven design: 128x128 tile, 256 threads, TM=TN=8 (3.11 rows/us).

#define BM 128
#define BN 128
#define BK 16

__global__ __launch_bounds__(256) void ffma_gemm_kernel(
    const float* __restrict__ input, const float* __restrict__ hx,
    const float* __restrict__ Wxh, const float* __restrict__ Whh,
    const float* __restrict__ bias)
{
    __shared__ float As[BK][BM];
    __shared__ float Bs[BK][BN];

    const int tid = threadIdx.x;
    const int tx = tid & 15;
    const int ty = tid >> 4;
    const int block_m = M_T + blockIdx.y * BM;
    const int block_n = blockIdx.x * BN;

    float acc[8][8];
#pragma unroll
    for (int i = 0; i < 8; i++)
#pragma unroll
        for (int j = 0; j < 8; j++) acc[i][j] = 0.0f;

    for (int k0 = 0; k0 < KTOT; k0 += BK) {
        const float* Ap; const float* Bp;
        int lda, ka;
        if (k0 < IN_DIM) { Ap = input; Bp = Wxh; lda = IN_DIM; ka = k0; }
        else             { Ap = hx;    Bp = Whh; lda = H_DIM;  ka = k0 - IN_DIM; }

#pragma unroll
        for (int r = 0; r < 2; r++) {
            int tt = tid + r * 256;
            int m = tt >> 2;
            int kq = (tt & 3) * 4;
            float4 v = *reinterpret_cast<const float4*>(
                Ap + (size_t)(block_m + m) * lda + ka + kq);
            As[kq + 0][m] = v.x; As[kq + 1][m] = v.y;
            As[kq + 2][m] = v.z; As[kq + 3][m] = v.w;
        }
#pragma unroll
        for (int r = 0; r < 2; r++) {
            int tt = tid + r * 256;
            int n = tt >> 2;
            int kq = (tt & 3) * 4;
            float4 v = *reinterpret_cast<const float4*>(
                Bp + (size_t)(block_n + n) * lda + ka + kq);
            Bs[kq + 0][n] = v.x; Bs[kq + 1][n] = v.y;
            Bs[kq + 2][n] = v.z; Bs[kq + 3][n] = v.w;
        }
        __syncthreads();

#pragma unroll
        for (int k = 0; k < BK; k++) {
            float a[8], b[8];
#pragma unroll
            for (int i = 0; i < 8; i++) a[i] = As[k][ty * 8 + i];
#pragma unroll
            for (int j = 0; j < 8; j++) b[j] = Bs[k][tx * 8 + j];
#pragma unroll
            for (int i = 0; i < 8; i++)
#pragma unroll
                for (int j = 0; j < 8; j++)
                    acc[i][j] = fmaf(a[i], b[j], acc[i][j]);
        }
        __syncthreads();
    }

#pragma unroll
    for (int i = 0; i < 8; i++) {
        size_t m = block_m + ty * 8 + i;
#pragma unroll
        for (int j = 0; j < 8; j += 4) {
            int n = block_n + tx * 8 + j;
            float4 v;
            v.x = acc[i][j + 0] + bias[n + 0];
            v.y = acc[i][j + 1] + bias[n + 1];
            v.z = acc[i][j + 2] + bias[n + 2];
            v.w = acc[i][j + 3] + bias[n + 3];
            *reinterpret_cast<float4*>(&g_gates[(m - M_T) * NGATE + n]) = v;
        }
    }
}

// ---------------- eltwise tail for FFMA rows ----------------

__global__ __launch_bounds__(256) void eltwise_tail_kernel(
    const float* __restrict__ time_, const float* __restrict__ cx,
    const float* __restrict__ tau, const float* __restrict__ s,
    const float* __restrict__ alpha_p, const float* __restrict__ rho_p,
    float* __restrict__ out)
{
    int idx = blockIdx.x * 256 + threadIdx.x;
    if (idx >= M_F * H_DIM) return;
    int b = M_T + (idx >> 10);
    int h = idx & (H_DIM - 1);

    float t = time_[b];
    float tu = tau[h];
    float phi = fmodf(t - s[h], tu) / tu;
    float alpha = alpha_p[0], rho = rho_p[0];
    float kg;
    if (phi < 0.5f * rho)      kg = 2.0f * phi / rho;
    else if (phi < rho)        kg = 2.0f - 2.0f * phi / rho;
    else                       kg = alpha * phi;

    const float* grow = g_gates + (size_t)(b - M_T) * NGATE + h;
    float gi = grow[0];
    float gf = grow[H_DIM];
    float gg = grow[2 * H_DIM];
    float go = grow[3 * H_DIM];

    float ft = sigf(gf + 1.0f - kg);
    float it = sigf(gi) * kg;
    float gt = tanhf(gg) * kg;
    float ot = sigf(go) * kg;

    float c = cx[(size_t)b * H_DIM + h];
    float cy = ft * c + it * gt;
    float hy = ot * tanhf(cy);

    out[(size_t)b * H_DIM + h] = hy;
    out[(size_t)B_DIM * H_DIM + (size_t)b * H_DIM + h] = cy;
}

// ---------------- launch (fork-join, two concurrent branches) -------------

extern "C" void kernel_launch(void* const* d_in, const int* in_sizes, int n_in,
                              void* d_out, int out_size) {
    const float* input = (const float*)d_in[0];
    const float* time_ = (const float*)d_in[1];
    const float* hx    = (const float*)d_in[2];
    const float* cx    = (const float*)d_in[3];
    const float* Wxh_w = (const float*)d_in[4];
    const float* Wxh_b = (const float*)d_in[5];
    const float* Whh_w = (const float*)d_in[6];
    const float* tau   = (const float*)d_in[7];
    const float* s     = (const float*)d_in[8];
    const float* alpha = (const float*)d_in[9];
    const float* rho   = (const float*)d_in[10];
    float* out = (float*)d_out;

    static cudaStream_t s1 = nullptr;
    static cudaEvent_t evF = nullptr, evJ = nullptr;
    if (s1 == nullptr) {
        cudaStreamCreateWithFlags(&s1, cudaStreamNonBlocking);
        cudaEventCreateWithFlags(&evF, cudaEventDisableTiming);
        cudaEventCreateWithFlags(&evJ, cudaEventDisableTiming);
        cudaFuncSetAttribute(gemm_fused_kernel,
                             cudaFuncAttributeMaxDynamicSharedMemorySize,
                             SMEM_BYTES);
    }

    // Fork: s1 runs prep + tensor GEMM (rows [0,M_T)); main stream runs the
    // FFMA path (rows [M_T,B_DIM)) concurrently.
    cudaEventRecord(evF, 0);
    cudaStreamWaitEvent(s1, evF, 0);

    prep_kernel<<<PREP_BLOCKS, 256, 0, s1>>>(input, hx, Wxh_w, Whh_w);
    {
        dim3 grid(NGATE / 64, M_T / 128);   // 64 x 27
        gemm_fused_kernel<<<grid, 256, SMEM_BYTES, s1>>>(
            time_, cx, tau, s, alpha, rho, Wxh_b, out);
    }
    cudaEventRecord(evJ, s1);

    {
        dim3 grid(NGATE / BN, M_F / BM);    // 32 x 5
        ffma_gemm_kernel<<<grid, 256>>>(input, hx, Wxh_w, Whh_w, Wxh_b);
    }
    eltwise_tail_kernel<<<(M_F * H_DIM + 255) / 256, 256>>>(
        time_, cx, tau, s, alpha, rho, out);

    // Join: main stream waits for the tensor branch.
    cudaStreamWaitEvent(0, evJ, 0);
}

// round 14
// speedup vs baseline: 1.5276x; 1.2714x over previous
#include <cuda_runtime.h>
#include <cuda_fp16.h>
#include <math.h>
#include <stdint.h>

#define B_DIM 4096
#define IN_DIM 512
#define H_DIM 1024
#define NGATE (4 * H_DIM)          // 4096
#define KTOT  (IN_DIM + H_DIM)     // 1536
#define KC 32                      // K per stage (fp16)
#define NSTAGE (KTOT / KC)         // 48

// fp16 hi/lo split copies of A = [input | hx] and B = permuted [Wxh | Whh]
__device__ __align__(16) __half g_Ah[(size_t)B_DIM * KTOT];
__device__ __align__(16) __half g_Al[(size_t)B_DIM * KTOT];
__device__ __align__(16) __half g_Bh[(size_t)NGATE * KTOT];
__device__ __align__(16) __half g_Bl[(size_t)NGATE * KTOT];

// ---------------- asm helpers (sm_80-compatible PTX only) ----------------

__device__ __forceinline__ uint32_t smem_u32(const void* p) {
    uint32_t a;
    asm("{ .reg .u64 t; cvta.to.shared.u64 t, %1; cvt.u32.u64 %0, t; }"
        : "=r"(a) : "l"(p));
    return a;
}

__device__ __forceinline__ void cpasync16(uint32_t dst, const void* src) {
    asm volatile("cp.async.cg.shared.global [%0], [%1], 16;"
                 :: "r"(dst), "l"(__cvta_generic_to_global(src)) : "memory");
}
#define CP_COMMIT() asm volatile("cp.async.commit_group;" ::: "memory")
#define CP_WAIT(n)  asm volatile("cp.async.wait_group %0;" :: "n"(n) : "memory")

__device__ __forceinline__ void ldsm_x4(uint32_t& r0, uint32_t& r1,
                                        uint32_t& r2, uint32_t& r3, uint32_t a) {
    asm volatile("ldmatrix.sync.aligned.m8n8.x4.shared.b16 {%0,%1,%2,%3}, [%4];"
                 : "=r"(r0), "=r"(r1), "=r"(r2), "=r"(r3) : "r"(a));
}

__device__ __forceinline__ void mma_f16(float* d, const uint32_t* a,
                                        const uint32_t* b) {
    asm volatile(
        "mma.sync.aligned.m16n8k16.row.col.f32.f16.f16.f32 "
        "{%0,%1,%2,%3}, {%4,%5,%6,%7}, {%8,%9}, {%0,%1,%2,%3};"
        : "+f"(d[0]), "+f"(d[1]), "+f"(d[2]), "+f"(d[3])
        : "r"(a[0]), "r"(a[1]), "r"(a[2]), "r"(a[3]), "r"(b[0]), "r"(b[1]));
}

__device__ __forceinline__ float sigf(float x) { return 1.0f / (1.0f + expf(-x)); }

// ---------------- fused prep kernel ----------------

struct alignas(16) Hf8 { __half h[8]; };

__device__ __forceinline__ void split8(const float* f, Hf8& hi, Hf8& lo) {
#pragma unroll
    for (int e = 0; e < 8; e++) {
        __half h = __float2half_rn(f[e]);
        hi.h[e] = h;
        lo.h[e] = __float2half_rn(f[e] - __half2float(h));
    }
}

// blocks [0,3072): A rows; blocks [3072,6144): B rows (permuted)
__global__ __launch_bounds__(256) void prep_kernel(
    const float* __restrict__ input, const float* __restrict__ hx,
    const float* __restrict__ Wxh, const float* __restrict__ Whh)
{
    int bid = blockIdx.x;
    if (bid < 3072) {
        int idx = bid * 256 + threadIdx.x;
        int row = idx / 192;
        int k = (idx % 192) * 8;
        const float* src = (k < IN_DIM) ? (input + (size_t)row * IN_DIM + k)
                                        : (hx + (size_t)row * H_DIM + (k - IN_DIM));
        float f[8];
        float4 v0 = ((const float4*)src)[0];
        float4 v1 = ((const float4*)src)[1];
        f[0]=v0.x; f[1]=v0.y; f[2]=v0.z; f[3]=v0.w;
        f[4]=v1.x; f[5]=v1.y; f[6]=v1.z; f[7]=v1.w;
        Hf8 hi, lo; split8(f, hi, lo);
        *(uint4*)&g_Ah[(size_t)row * KTOT + k] = *(const uint4*)&hi;
        *(uint4*)&g_Al[(size_t)row * KTOT + k] = *(const uint4*)&lo;
    } else {
        int idx = (bid - 3072) * 256 + threadIdx.x;
        int rowp = idx / 192;                 // row' = (h>>3)*32 + g*8 + (h&7)
        int k = (idx % 192) * 8;
        int g = (rowp >> 3) & 3;
        int h = ((rowp >> 5) << 3) | (rowp & 7);
        int orig = g * H_DIM + h;
        const float* src = (k < IN_DIM) ? (Wxh + (size_t)orig * IN_DIM + k)
                                        : (Whh + (size_t)orig * H_DIM + (k - IN_DIM));
        float f[8];
        float4 v0 = ((const float4*)src)[0];
        float4 v1 = ((const float4*)src)[1];
        f[0]=v0.x; f[1]=v0.y; f[2]=v0.z; f[3]=v0.w;
        f[4]=v1.x; f[5]=v1.y; f[6]=v1.z; f[7]=v1.w;
        Hf8 hi, lo; split8(f, hi, lo);
        *(uint4*)&g_Bh[(size_t)rowp * KTOT + k] = *(const uint4*)&hi;
        *(uint4*)&g_Bl[(size_t)rowp * KTOT + k] = *(const uint4*)&lo;
    }
}

// ---------------- fused HMMA GEMM + phased-LSTM epilogue ----------------
// CTA tile 128(M) x 64(N), 8 warps (warp tile 32x32), 2 CTAs/SM.
// Fragment double-buffering: both k-steps' ldsm issue before the MMA bursts.

#define ROW_B 80                       // 64B data + 16B pad (conflict-free)
#define ATILE (128 * ROW_B)            // 10240
#define BTILE (64 * ROW_B)             // 5120
#define STAGE_SZ (2 * ATILE + 2 * BTILE)   // 30720
#define NRING 3
#define SMEM_BYTES (NRING * STAGE_SZ)  // 92160

__global__ __launch_bounds__(256, 2) void gemm_fused_kernel(
    const float* __restrict__ time_,  // [B]
    const float* __restrict__ cx,     // [B, H]
    const float* __restrict__ tau,
    const float* __restrict__ s,
    const float* __restrict__ alpha_p,
    const float* __restrict__ rho_p,
    const float* __restrict__ bias,   // [4H]
    float* __restrict__ out)          // hy then cy
{
    extern __shared__ char smem[];
    const uint32_t sb = smem_u32(smem);
    const int tid = threadIdx.x;
    const int wid = tid >> 5;
    const int lane = tid & 31;
    const int wm = wid >> 1;
    const int wn = wid & 1;

    const int m0 = blockIdx.y * 128;
    const int n0 = blockIdx.x * 64;

    const int g_row = tid >> 2;
    const int g_c4  = tid & 3;
    const uint32_t st_off   = (uint32_t)g_row * ROW_B + g_c4 * 16;
    const uint32_t st_off64 = st_off + 64 * ROW_B;
    const int g_kelem = g_c4 * 8;

    const __half* pAh  = g_Ah + (size_t)(m0 + g_row) * KTOT + g_kelem;
    const __half* pAl  = g_Al + (size_t)(m0 + g_row) * KTOT + g_kelem;
    const size_t row64 = (size_t)64 * KTOT;
    const __half* pBh  = g_Bh + (size_t)(n0 + g_row) * KTOT + g_kelem;
    const __half* pBl  = g_Bl + (size_t)(n0 + g_row) * KTOT + g_kelem;

    const int l15 = lane & 15;
    uint32_t a_off[2];
#pragma unroll
    for (int i = 0; i < 2; i++)
        a_off[i] = (uint32_t)(wm * 32 + i * 16 + l15) * ROW_B + (lane >> 4) * 16;
    uint32_t b_off[2];
    {
        int l7 = lane & 7;
        int rhalf = (lane >> 4) & 1;
        int chalf = (lane >> 3) & 1;
#pragma unroll
        for (int j = 0; j < 2; j++)
            b_off[j] = (uint32_t)(wn * 32 + j * 16 + rhalf * 8 + l7) * ROW_B + chalf * 16;
    }

    float acc[2][4][4];
#pragma unroll
    for (int i = 0; i < 2; i++)
#pragma unroll
        for (int nb = 0; nb < 4; nb++)
#pragma unroll
            for (int e = 0; e < 4; e++) acc[i][nb][e] = 0.0f;

    // double-buffered fragments: [kstep buf][...]
    uint32_t ahf[2][2][4], alf[2][2][4], bhf[2][4][2], blf[2][4][2];

#define LOAD_FRAGS(B, AHB, ALB, BHB, BLB, KO) do {                           \
    _Pragma("unroll")                                                        \
    for (int j = 0; j < 2; j++)                                              \
        ldsm_x4(bhf[B][2*j][0], bhf[B][2*j][1], bhf[B][2*j+1][0],            \
                bhf[B][2*j+1][1], (BHB) + b_off[j] + (KO));                  \
    _Pragma("unroll")                                                        \
    for (int i = 0; i < 2; i++)                                              \
        ldsm_x4(ahf[B][i][0], ahf[B][i][1], ahf[B][i][2], ahf[B][i][3],      \
                (AHB) + a_off[i] + (KO));                                    \
    _Pragma("unroll")                                                        \
    for (int j = 0; j < 2; j++)                                              \
        ldsm_x4(blf[B][2*j][0], blf[B][2*j][1], blf[B][2*j+1][0],            \
                blf[B][2*j+1][1], (BLB) + b_off[j] + (KO));                  \
    _Pragma("unroll")                                                        \
    for (int i = 0; i < 2; i++)                                              \
        ldsm_x4(alf[B][i][0], alf[B][i][1], alf[B][i][2], alf[B][i][3],      \
                (ALB) + a_off[i] + (KO));                                    \
} while (0)

#define MMA_BURST(B) do {                                                    \
    _Pragma("unroll")                                                        \
    for (int i = 0; i < 2; i++)                                              \
        _Pragma("unroll")                                                    \
        for (int nb = 0; nb < 4; nb++)                                       \
            mma_f16(acc[i][nb], ahf[B][i], bhf[B][nb]);                      \
    _Pragma("unroll")                                                        \
    for (int i = 0; i < 2; i++)                                              \
        _Pragma("unroll")                                                    \
        for (int nb = 0; nb < 4; nb++)                                       \
            mma_f16(acc[i][nb], ahf[B][i], blf[B][nb]);                      \
    _Pragma("unroll")                                                        \
    for (int i = 0; i < 2; i++)                                              \
        _Pragma("unroll")                                                    \
        for (int nb = 0; nb < 4; nb++)                                       \
            mma_f16(acc[i][nb], alf[B][i], bhf[B][nb]);                      \
} while (0)

#define ISSUE_STAGE(C, BUF) do {                                             \
    uint32_t base_ = sb + (uint32_t)(BUF) * STAGE_SZ;                        \
    size_t ke_ = (size_t)(C) * KC;                                           \
    cpasync16(base_ + st_off,                      pAh + ke_);               \
    cpasync16(base_ + st_off64,                    pAh + row64 + ke_);       \
    cpasync16(base_ + ATILE + st_off,              pAl + ke_);               \
    cpasync16(base_ + ATILE + st_off64,            pAl + row64 + ke_);       \
    cpasync16(base_ + 2*ATILE + st_off,            pBh + ke_);               \
    cpasync16(base_ + 2*ATILE + BTILE + st_off,    pBl + ke_);               \
    CP_COMMIT();                                                             \
} while (0)

    ISSUE_STAGE(0, 0);
    ISSUE_STAGE(1, 1);

    for (int c = 0; c < NSTAGE; c++) {
        const int buf = c % 3;
        if (c + 1 < NSTAGE) { CP_WAIT(1); }
        else                { CP_WAIT(0); }
        __syncthreads();
        if (c + 2 < NSTAGE)
            ISSUE_STAGE(c + 2, (c + 2) % 3);

        const uint32_t ahb = sb + (uint32_t)buf * STAGE_SZ;
        const uint32_t alb = ahb + ATILE;
        const uint32_t bhb = ahb + 2 * ATILE;
        const uint32_t blb = bhb + BTILE;

        // issue ALL fragment loads for both k-steps, then the two MMA bursts;
        // burst 1's operands were requested 24 MMAs before they're consumed.
        LOAD_FRAGS(0, ahb, alb, bhb, blb, 0);
        LOAD_FRAGS(1, ahb, alb, bhb, blb, 32);
        MMA_BURST(0);
        MMA_BURST(1);
    }

    // ---- fused epilogue ----
    const int t = lane & 3;
    const int grow = lane >> 2;
    const int hb = ((n0 + wn * 32) >> 2) + 2 * t;

    const float alpha = alpha_p[0];
    const float rho = rho_p[0];
    const float inv_rho = 2.0f / rho;
    const float tu[2] = {tau[hb], tau[hb + 1]};
    const float sh[2] = {s[hb], s[hb + 1]};
    float bi[4][2];
#pragma unroll
    for (int g = 0; g < 4; g++) {
        bi[g][0] = bias[g * H_DIM + hb];
        bi[g][1] = bias[g * H_DIM + hb + 1];
    }

#pragma unroll
    for (int i = 0; i < 2; i++) {
#pragma unroll
        for (int rsel = 0; rsel < 2; rsel++) {
            const int r = m0 + wm * 32 + i * 16 + grow + rsel * 8;
            const float tt = time_[r];
            const float2 cx2 = *(const float2*)&cx[(size_t)r * H_DIM + hb];
            const float cxa[2] = {cx2.x, cx2.y};
            float hy2[2], cy2[2];
#pragma unroll
            for (int e = 0; e < 2; e++) {
                const int d = rsel * 2 + e;
                float gi = acc[i][0][d] + bi[0][e];
                float gf = acc[i][1][d] + bi[1][e];
                float gg = acc[i][2][d] + bi[2][e];
                float go = acc[i][3][d] + bi[3][e];
                float phi = fmodf(tt - sh[e], tu[e]) / tu[e];
                float kg;
                if (phi < 0.5f * rho)      kg = phi * inv_rho;
                else if (phi < rho)        kg = 2.0f - phi * inv_rho;
                else                       kg = alpha * phi;
                float ft = sigf(gf + 1.0f - kg);
                float it = sigf(gi) * kg;
                float gt = tanhf(gg) * kg;
                float ot = sigf(go) * kg;
                float cyv = ft * cxa[e] + it * gt;
                cy2[e] = cyv;
                hy2[e] = ot * tanhf(cyv);
            }
            *(float2*)&out[(size_t)r * H_DIM + hb] = make_float2(hy2[0], hy2[1]);
            *(float2*)&out[(size_t)B_DIM * H_DIM + (size_t)r * H_DIM + hb] =
                make_float2(cy2[0], cy2[1]);
        }
    }
}

// ---------------- launch ----------------

extern "C" void kernel_launch(void* const* d_in, const int* in_sizes, int n_in,
                              void* d_out, int out_size) {
    const float* input = (const float*)d_in[0];
    const float* time_ = (const float*)d_in[1];
    const float* hx    = (const float*)d_in[2];
    const float* cx    = (const float*)d_in[3];
    const float* Wxh_w = (const float*)d_in[4];
    const float* Wxh_b = (const float*)d_in[5];
    const float* Whh_w = (const float*)d_in[6];
    const float* tau   = (const float*)d_in[7];
    const float* s     = (const float*)d_in[8];
    const float* alpha = (const float*)d_in[9];
    const float* rho   = (const float*)d_in[10];
    float* out = (float*)d_out;

    cudaFuncSetAttribute(gemm_fused_kernel,
                         cudaFuncAttributeMaxDynamicSharedMemorySize, SMEM_BYTES);

    prep_kernel<<<6144, 256>>>(input, hx, Wxh_w, Whh_w);

    dim3 grid(NGATE / 64, B_DIM / 128);   // 64 x 32
    gemm_fused_kernel<<<grid, 256, SMEM_BYTES>>>(
        time_, cx, tau, s, alpha, rho, Wxh_b, out);
}

// round 15
// speedup vs baseline: 1.5580x; 1.0199x over previous
#include <cuda_runtime.h>
#include <cuda_fp16.h>
#include <math.h>
#include <stdint.h>

#define B_DIM 4096
#define IN_DIM 512
#define H_DIM 1024
#define NGATE (4 * H_DIM)          // 4096
#define KTOT  (IN_DIM + H_DIM)     // 1536
#define KC 32                      // K per stage (fp16)
#define NSTAGE (KTOT / KC)         // 48

// fp16 hi/lo split copies of A = [input | hx] and B = permuted [Wxh | Whh]
__device__ __align__(16) __half g_Ah[(size_t)B_DIM * KTOT];
__device__ __align__(16) __half g_Al[(size_t)B_DIM * KTOT];
__device__ __align__(16) __half g_Bh[(size_t)NGATE * KTOT];
__device__ __align__(16) __half g_Bl[(size_t)NGATE * KTOT];

// ---------------- asm helpers (sm_80-compatible PTX only) ----------------

__device__ __forceinline__ uint32_t smem_u32(const void* p) {
    uint32_t a;
    asm("{ .reg .u64 t; cvta.to.shared.u64 t, %1; cvt.u32.u64 %0, t; }"
        : "=r"(a) : "l"(p));
    return a;
}

__device__ __forceinline__ void cpasync16(uint32_t dst, const void* src) {
    asm volatile("cp.async.cg.shared.global [%0], [%1], 16;"
                 :: "r"(dst), "l"(__cvta_generic_to_global(src)) : "memory");
}
#define CP_COMMIT() asm volatile("cp.async.commit_group;" ::: "memory")
#define CP_WAIT(n)  asm volatile("cp.async.wait_group %0;" :: "n"(n) : "memory")

__device__ __forceinline__ void ldsm_x4(uint32_t& r0, uint32_t& r1,
                                        uint32_t& r2, uint32_t& r3, uint32_t a) {
    asm volatile("ldmatrix.sync.aligned.m8n8.x4.shared.b16 {%0,%1,%2,%3}, [%4];"
                 : "=r"(r0), "=r"(r1), "=r"(r2), "=r"(r3) : "r"(a));
}

__device__ __forceinline__ void mma_f16(float* d, const uint32_t* a,
                                        const uint32_t* b) {
    asm volatile(
        "mma.sync.aligned.m16n8k16.row.col.f32.f16.f16.f32 "
        "{%0,%1,%2,%3}, {%4,%5,%6,%7}, {%8,%9}, {%0,%1,%2,%3};"
        : "+f"(d[0]), "+f"(d[1]), "+f"(d[2]), "+f"(d[3])
        : "r"(a[0]), "r"(a[1]), "r"(a[2]), "r"(a[3]), "r"(b[0]), "r"(b[1]));
}

__device__ __forceinline__ float sigf(float x) { return 1.0f / (1.0f + expf(-x)); }

// ---------------- fused prep kernel ----------------

struct alignas(16) Hf8 { __half h[8]; };

__device__ __forceinline__ void split8(const float* f, Hf8& hi, Hf8& lo) {
#pragma unroll
    for (int e = 0; e < 8; e++) {
        __half h = __float2half_rn(f[e]);
        hi.h[e] = h;
        lo.h[e] = __float2half_rn(f[e] - __half2float(h));
    }
}

// blocks [0,3072): A rows; blocks [3072,6144): B rows (permuted)
__global__ __launch_bounds__(256) void prep_kernel(
    const float* __restrict__ input, const float* __restrict__ hx,
    const float* __restrict__ Wxh, const float* __restrict__ Whh)
{
    int bid = blockIdx.x;
    if (bid < 3072) {
        int idx = bid * 256 + threadIdx.x;
        int row = idx / 192;
        int k = (idx % 192) * 8;
        const float* src = (k < IN_DIM) ? (input + (size_t)row * IN_DIM + k)
                                        : (hx + (size_t)row * H_DIM + (k - IN_DIM));
        float f[8];
        float4 v0 = ((const float4*)src)[0];
        float4 v1 = ((const float4*)src)[1];
        f[0]=v0.x; f[1]=v0.y; f[2]=v0.z; f[3]=v0.w;
        f[4]=v1.x; f[5]=v1.y; f[6]=v1.z; f[7]=v1.w;
        Hf8 hi, lo; split8(f, hi, lo);
        *(uint4*)&g_Ah[(size_t)row * KTOT + k] = *(const uint4*)&hi;
        *(uint4*)&g_Al[(size_t)row * KTOT + k] = *(const uint4*)&lo;
    } else {
        int idx = (bid - 3072) * 256 + threadIdx.x;
        int rowp = idx / 192;                 // row' = (h>>3)*32 + g*8 + (h&7)
        int k = (idx % 192) * 8;
        int g = (rowp >> 3) & 3;
        int h = ((rowp >> 5) << 3) | (rowp & 7);
        int orig = g * H_DIM + h;
        const float* src = (k < IN_DIM) ? (Wxh + (size_t)orig * IN_DIM + k)
                                        : (Whh + (size_t)orig * H_DIM + (k - IN_DIM));
        float f[8];
        float4 v0 = ((const float4*)src)[0];
        float4 v1 = ((const float4*)src)[1];
        f[0]=v0.x; f[1]=v0.y; f[2]=v0.z; f[3]=v0.w;
        f[4]=v1.x; f[5]=v1.y; f[6]=v1.z; f[7]=v1.w;
        Hf8 hi, lo; split8(f, hi, lo);
        *(uint4*)&g_Bh[(size_t)rowp * KTOT + k] = *(const uint4*)&hi;
        *(uint4*)&g_Bl[(size_t)rowp * KTOT + k] = *(const uint4*)&lo;
    }
}

// ---------------- fused HMMA GEMM + phased-LSTM epilogue ----------------
// CTA tile 128(M) x 64(N), 8 warps (warp tile 32x32), ring-2, 3 CTAs/SM
// (6 warps per SMSP — testing the warp-level-parallelism axis).

#define ROW_B 80                       // 64B data + 16B pad (conflict-free)
#define ATILE (128 * ROW_B)            // 10240
#define BTILE (64 * ROW_B)             // 5120
#define STAGE_SZ (2 * ATILE + 2 * BTILE)   // 30720
#define NRING 2
#define SMEM_BYTES (NRING * STAGE_SZ)  // 61440  (x3 CTAs = 184320 <= 228K)

__global__ __launch_bounds__(256, 3) void gemm_fused_kernel(
    const float* __restrict__ time_,  // [B]
    const float* __restrict__ cx,     // [B, H]
    const float* __restrict__ tau,
    const float* __restrict__ s,
    const float* __restrict__ alpha_p,
    const float* __restrict__ rho_p,
    const float* __restrict__ bias,   // [4H]
    float* __restrict__ out)          // hy then cy
{
    extern __shared__ char smem[];
    const uint32_t sb = smem_u32(smem);
    const int tid = threadIdx.x;
    const int wid = tid >> 5;
    const int lane = tid & 31;
    const int wm = wid >> 1;          // 0..3  warp M base = wm*32
    const int wn = wid & 1;           // 0..1  warp N base = wn*32

    const int m0 = blockIdx.y * 128;
    const int n0 = blockIdx.x * 64;

    // --- global-load mapping ---
    const int g_row = tid >> 2;        // 0..63
    const int g_c4  = tid & 3;         // 0..3
    const uint32_t st_off   = (uint32_t)g_row * ROW_B + g_c4 * 16;
    const uint32_t st_off64 = st_off + 64 * ROW_B;
    const int g_kelem = g_c4 * 8;

    const __half* pAh  = g_Ah + (size_t)(m0 + g_row) * KTOT + g_kelem;
    const __half* pAl  = g_Al + (size_t)(m0 + g_row) * KTOT + g_kelem;
    const size_t row64 = (size_t)64 * KTOT;
    const __half* pBh  = g_Bh + (size_t)(n0 + g_row) * KTOT + g_kelem;
    const __half* pBl  = g_Bl + (size_t)(n0 + g_row) * KTOT + g_kelem;

    // --- ldmatrix lane offsets ---
    const int l15 = lane & 15;
    uint32_t a_off[2];
#pragma unroll
    for (int i = 0; i < 2; i++)
        a_off[i] = (uint32_t)(wm * 32 + i * 16 + l15) * ROW_B + (lane >> 4) * 16;
    uint32_t b_off[2];
    {
        int l7 = lane & 7;
        int rhalf = (lane >> 4) & 1;
        int chalf = (lane >> 3) & 1;
#pragma unroll
        for (int j = 0; j < 2; j++)
            b_off[j] = (uint32_t)(wn * 32 + j * 16 + rhalf * 8 + l7) * ROW_B + chalf * 16;
    }

    float acc[2][4][4];
#pragma unroll
    for (int i = 0; i < 2; i++)
#pragma unroll
        for (int nb = 0; nb < 4; nb++)
#pragma unroll
            for (int e = 0; e < 4; e++) acc[i][nb][e] = 0.0f;

#define ISSUE_STAGE(C, BUF) do {                                            \
    uint32_t base_ = sb + (uint32_t)(BUF) * STAGE_SZ;                       \
    size_t ke_ = (size_t)(C) * KC;                                          \
    cpasync16(base_ + st_off,                      pAh + ke_);              \
    cpasync16(base_ + st_off64,                    pAh + row64 + ke_);      \
    cpasync16(base_ + ATILE + st_off,              pAl + ke_);              \
    cpasync16(base_ + ATILE + st_off64,            pAl + row64 + ke_);      \
    cpasync16(base_ + 2*ATILE + st_off,            pBh + ke_);              \
    cpasync16(base_ + 2*ATILE + BTILE + st_off,    pBl + ke_);              \
    CP_COMMIT();                                                            \
} while (0)

    ISSUE_STAGE(0, 0);
    ISSUE_STAGE(1, 1);

    for (int c = 0; c < NSTAGE; c++) {
        const int buf = c & 1;

        // Pending groups at top of iter c: {c, c+1}; require stage c done.
        if (c + 1 < NSTAGE) { CP_WAIT(1); }
        else                { CP_WAIT(0); }
        __syncthreads();                 // stage c data visible to all warps

        const uint32_t ahb = sb + (uint32_t)buf * STAGE_SZ;
        const uint32_t alb = ahb + ATILE;
        const uint32_t bhb = ahb + 2 * ATILE;
        const uint32_t blb = bhb + BTILE;

#pragma unroll
        for (int ks = 0; ks < 2; ks++) {
            const uint32_t ko = ks * 32;
            // interleaved loads/bursts: max 24 live fragment regs
            uint32_t ah[2][4], bh[4][2];
#pragma unroll
            for (int j = 0; j < 2; j++)
                ldsm_x4(bh[2*j][0], bh[2*j][1], bh[2*j+1][0], bh[2*j+1][1],
                        bhb + b_off[j] + ko);
#pragma unroll
            for (int i = 0; i < 2; i++)
                ldsm_x4(ah[i][0], ah[i][1], ah[i][2], ah[i][3],
                        ahb + a_off[i] + ko);
#pragma unroll
            for (int i = 0; i < 2; i++)
#pragma unroll
                for (int nb = 0; nb < 4; nb++)
                    mma_f16(acc[i][nb], ah[i], bh[nb]);

            uint32_t bl[4][2];
#pragma unroll
            for (int j = 0; j < 2; j++)
                ldsm_x4(bl[2*j][0], bl[2*j][1], bl[2*j+1][0], bl[2*j+1][1],
                        blb + b_off[j] + ko);
#pragma unroll
            for (int i = 0; i < 2; i++)
#pragma unroll
                for (int nb = 0; nb < 4; nb++)
                    mma_f16(acc[i][nb], ah[i], bl[nb]);

            uint32_t al[2][4];
#pragma unroll
            for (int i = 0; i < 2; i++)
                ldsm_x4(al[i][0], al[i][1], al[i][2], al[i][3],
                        alb + a_off[i] + ko);
#pragma unroll
            for (int i = 0; i < 2; i++)
#pragma unroll
                for (int nb = 0; nb < 4; nb++)
                    mma_f16(acc[i][nb], al[i], bh[nb]);
        }

        // All warps done reading buf; safe to overwrite with stage c+2.
        __syncthreads();
        if (c + 2 < NSTAGE)
            ISSUE_STAGE(c + 2, buf);
    }

    // ---- fused epilogue ----
    const int t = lane & 3;
    const int grow = lane >> 2;
    const int hb = ((n0 + wn * 32) >> 2) + 2 * t;

    const float alpha = alpha_p[0];
    const float rho = rho_p[0];
    const float inv_rho = 2.0f / rho;
    const float tu[2] = {tau[hb], tau[hb + 1]};
    const float sh[2] = {s[hb], s[hb + 1]};
    float bi[4][2];
#pragma unroll
    for (int g = 0; g < 4; g++) {
        bi[g][0] = bias[g * H_DIM + hb];
        bi[g][1] = bias[g * H_DIM + hb + 1];
    }

#pragma unroll
    for (int i = 0; i < 2; i++) {
#pragma unroll
        for (int rsel = 0; rsel < 2; rsel++) {
            const int r = m0 + wm * 32 + i * 16 + grow + rsel * 8;
            const float tt = time_[r];
            const float2 cx2 = *(const float2*)&cx[(size_t)r * H_DIM + hb];
            const float cxa[2] = {cx2.x, cx2.y};
            float hy2[2], cy2[2];
#pragma unroll
            for (int e = 0; e < 2; e++) {
                const int d = rsel * 2 + e;
                float gi = acc[i][0][d] + bi[0][e];
                float gf = acc[i][1][d] + bi[1][e];
                float gg = acc[i][2][d] + bi[2][e];
                float go = acc[i][3][d] + bi[3][e];
                float phi = fmodf(tt - sh[e], tu[e]) / tu[e];
                float kg;
                if (phi < 0.5f * rho)      kg = phi * inv_rho;
                else if (phi < rho)        kg = 2.0f - phi * inv_rho;
                else                       kg = alpha * phi;
                float ft = sigf(gf + 1.0f - kg);
                float it = sigf(gi) * kg;
                float gt = tanhf(gg) * kg;
                float ot = sigf(go) * kg;
                float cyv = ft * cxa[e] + it * gt;
                cy2[e] = cyv;
                hy2[e] = ot * tanhf(cyv);
            }
            *(float2*)&out[(size_t)r * H_DIM + hb] = make_float2(hy2[0], hy2[1]);
            *(float2*)&out[(size_t)B_DIM * H_DIM + (size_t)r * H_DIM + hb] =
                make_float2(cy2[0], cy2[1]);
        }
    }
}

// ---------------- launch ----------------

extern "C" void kernel_launch(void* const* d_in, const int* in_sizes, int n_in,
                              void* d_out, int out_size) {
    const float* input = (const float*)d_in[0];
    const float* time_ = (const float*)d_in[1];
    const float* hx    = (const float*)d_in[2];
    const float* cx    = (const float*)d_in[3];
    const float* Wxh_w = (const float*)d_in[4];
    const float* Wxh_b = (const float*)d_in[5];
    const float* Whh_w = (const float*)d_in[6];
    const float* tau   = (const float*)d_in[7];
    const float* s     = (const float*)d_in[8];
    const float* alpha = (const float*)d_in[9];
    const float* rho   = (const float*)d_in[10];
    float* out = (float*)d_out;

    cudaFuncSetAttribute(gemm_fused_kernel,
                         cudaFuncAttributeMaxDynamicSharedMemorySize, SMEM_BYTES);

    prep_kernel<<<6144, 256>>>(input, hx, Wxh_w, Whh_w);

    dim3 grid(NGATE / 64, B_DIM / 128);   // 64 x 32
    gemm_fused_kernel<<<grid, 256, SMEM_BYTES>>>(
        time_, cx, tau, s, alpha, rho, Wxh_b, out);
}